// round 13
// baseline (speedup 1.0000x reference)
#include <cuda_runtime.h>
#include <cstdint>

// ---------------------------------------------------------------------------
// HausdorffLoss: B=8, N=M=4096, 3-D points. Single fused dense kernel.
// d[b,n,m] = x2[n] + y2[m] - 2*dot(x_n, y_m)
// out = sum_b max( max_n min_m d, max_m min_n d )
//
// Round-12: occupancy push. RN=2 (256 rows/block), 42-reg cap via
// __launch_bounds__(128,12) -> 12 blocks/SM = 75% occ to feed the FFMA2
// pipe (rt=3 from register-bank pressure: 3 even + 3 odd distinct regs).
// xsq recomputed in the epilogue from the packed px registers (no live
// xsq regs in the hot loop). grid (16,32,16) = 8192 fine-grained blocks.
// Cross-block per-row min via order-inverted-key atomicMax (identity 0).
// Group ticket -> group max -> per-batch atomicMax -> global ticket ->
// final sum. All global state reset each call (graph-replay invariant).
// ---------------------------------------------------------------------------

#define NPOINT 4096
#define T      128                 // threads per block
#define RN     2                   // rows per thread
#define BN     (T * RN)            // 256 rows per block
#define ROWB   (NPOINT / BN)       // 16 row-blocks
#define CS     32                  // column splits
#define CPB    (NPOINT / CS)       // 128 cols per block
#define TM     CPB                 // tile = whole slice (2KB)
#define NGRP   16                  // B*2 (b,dir) groups
#define GBLK   (ROWB * CS)         // blocks per group = 512

#define FMA2(d, a, b, c) \
    asm("fma.rn.f32x2 %0, %1, %2, %3;" : "=l"(d) : "l"(a), "l"(b), "l"(c))
#define PACK2(o, x) \
    asm("mov.b64 %0, {%1, %1};" : "=l"(o) : "f"(x))
#define UNPACK2(lo, hi, v) \
    asm("mov.b64 {%0, %1}, %2;" : "=f"(lo), "=f"(hi) : "l"(v))

// Monotone map: smaller float <=> LARGER unsigned key (row min == atomicMax).
// Every real float maps to key > 0, so 0 is the identity/reset state.
__device__ __forceinline__ unsigned map_min(float f) {
    unsigned u = __float_as_uint(f);
    return ((int)u < 0) ? u : (~u & 0x7FFFFFFFu);
}
__device__ __forceinline__ float unmap_min(unsigned s) {
    return ((int)s < 0) ? __uint_as_float(s)
                        : __uint_as_float(~s & 0x7FFFFFFFu);
}

__device__ unsigned g_cmb[NGRP][NPOINT];  // combined row-min keys (reset 0)
__device__ int      g_grp[NGRP];          // per-group tickets (reset 0)
__device__ float    g_bmax[16];           // per-batch max >= 0 (reset 0)
__device__ int      g_done;               // finalizer ticket (reset 0)

__global__ void __launch_bounds__(T, 12)
hd_main(const float* __restrict__ p1, const float* __restrict__ p2,
        float* __restrict__ out, int nb) {
    const int tid = threadIdx.x;
    const int z   = blockIdx.z;          // b*2 + dir
    const int b   = z >> 1;
    const int dir = z & 1;

    const float* rows = (dir == 0 ? p1 : p2) + (size_t)b * NPOINT * 3;
    const float* cols = (dir == 0 ? p2 : p1) + (size_t)b * NPOINT * 3;

    // Per-thread row points, coords broadcast-packed for f32x2.
    // (x^2 is recomputed from these in the epilogue - no extra live regs.)
    unsigned long long px0[RN], px1[RN], px2[RN];
    float rmE[RN], rmO[RN];

#pragma unroll
    for (int r = 0; r < RN; r++) {
        const int n = blockIdx.x * BN + r * T + tid;
        const float* pr = rows + (size_t)n * 3;
        PACK2(px0[r], pr[0]);
        PACK2(px1[r], pr[1]);
        PACK2(px2[r], pr[2]);
        rmE[r] = 3.4e38f;
        rmO[r] = 3.4e38f;
    }

    // Shared tile: col pair j -> entry 2j   = {-2y0[e],-2y0[o],-2y1[e],-2y1[o]}
    //                            entry 2j+1 = {-2y2[e],-2y2[o],  y2[e],  y2[o]}
    __shared__ ulonglong2 sAB[TM];
    __shared__ unsigned   sred[T / 32];

    {
        const int idx = tid;             // TM == T: one point per thread
        const float* pc = cols + (size_t)(blockIdx.y * CPB + idx) * 3;
        const float y0 = pc[0], y1 = pc[1], y2 = pc[2];
        const float ysq = y0 * y0 + y1 * y1 + y2 * y2;
        const int j = idx >> 1, l = idx & 1;
        float* A  = reinterpret_cast<float*>(&sAB[2 * j]);
        float* Bv = reinterpret_cast<float*>(&sAB[2 * j + 1]);
        A[l]      = -2.0f * y0;
        A[2 + l]  = -2.0f * y1;
        Bv[l]     = -2.0f * y2;
        Bv[2 + l] = ysq;
    }
    __syncthreads();

    const ulonglong2* sp = sAB;
#pragma unroll 8
    for (int j = 0; j < TM / 2; j++, sp += 2) {
        const ulonglong2 va = sp[0];
        const ulonglong2 vb = sp[1];
#pragma unroll
        for (int r = 0; r < RN; r++) {
            unsigned long long t0r, t1r, acc;
            FMA2(t0r, px2[r], vb.x, vb.y);   // -2*x2*y2 + y^2
            FMA2(t1r, px1[r], va.y, t0r);    // + -2*x1*y1
            FMA2(acc, px0[r], va.x, t1r);    // + -2*x0*y0
            float lo, hi;
            UNPACK2(lo, hi, acc);
            rmE[r] = fminf(rmE[r], lo);
            rmO[r] = fminf(rmO[r], hi);
        }
    }

    // Combine this slice's row mins into the global per-row key array.
#pragma unroll
    for (int r = 0; r < RN; r++) {
        const int n = blockIdx.x * BN + r * T + tid;
        float a0, a1, a2, dummy;
        UNPACK2(a0, dummy, px0[r]);
        UNPACK2(a1, dummy, px1[r]);
        UNPACK2(a2, dummy, px2[r]);
        const float xsq = a0 * a0 + a1 * a1 + a2 * a2;
        const float d = xsq + fminf(rmE[r], rmO[r]);
        atomicMax(&g_cmb[z][n], map_min(d));
    }
    __threadfence();
    __syncthreads();

    // Group ticket: last of the GBLK blocks in this (b,dir) finalizes.
    __shared__ int s_last;
    if (tid == 0)
        s_last = (atomicAdd(&g_grp[z], 1) == GBLK - 1);
    __syncthreads();
    if (!s_last) return;
    __threadfence();

    // Group finalize: max over rows of row-min == unmap(min over keys).
    unsigned kmin = 0xFFFFFFFFu;
    for (int i = tid; i < NPOINT; i += T) {
        kmin = min(kmin, g_cmb[z][i]);
        g_cmb[z][i] = 0u;                       // reset for next replay
    }
#pragma unroll
    for (int off = 16; off > 0; off >>= 1)
        kmin = min(kmin, __shfl_xor_sync(0xffffffffu, kmin, off));
    if ((tid & 31) == 0) sred[tid >> 5] = kmin;
    __syncthreads();

    if (tid == 0) {
        unsigned km = sred[0];
#pragma unroll
        for (int w = 1; w < T / 32; w++) km = min(km, sred[w]);
        float m = fmaxf(unmap_min(km), 0.0f);   // true max > 0
        atomicMax(reinterpret_cast<int*>(&g_bmax[b]), __float_as_int(m));
        g_grp[z] = 0;                           // reset group ticket
        __threadfence();
        if (atomicAdd(&g_done, 1) == NGRP - 1) {
            __threadfence();
            float s = 0.0f;
            for (int i = 0; i < nb; i++) {
                s += g_bmax[i];
                g_bmax[i] = 0.0f;               // reset
            }
            out[0] = s;
            __threadfence();
            atomicExch(&g_done, 0);             // reset
        }
    }
}

extern "C" void kernel_launch(void* const* d_in, const int* in_sizes, int n_in,
                              void* d_out, int out_size) {
    const float* p1 = (const float*)d_in[0];
    const float* p2 = (const float*)d_in[1];
    float* out = (float*)d_out;

    const int B = in_sizes[0] / (NPOINT * 3);
    dim3 grid(ROWB, CS, B * 2);
    hd_main<<<grid, T>>>(p1, p2, out, B);
}

// round 14
// speedup vs baseline: 1.0501x; 1.0501x over previous
#include <cuda_runtime.h>
#include <cstdint>

// ---------------------------------------------------------------------------
// HausdorffLoss: B=8, N=M=4096, 3-D points. Single fused dense kernel.
// d[b,n,m] = x2[n] + y2[m] - 2*dot(x_n, y_m)
// out = sum_b max( max_n min_m d, max_m min_n d )
//
// Round-14: RN=4 mix (best instr/pair) at 10 blocks/SM. 51-reg cap via
// __launch_bounds__(128,10); xsq recomputed in the epilogue from the packed
// px registers so no xsq regs stay live through the hot loop.
// grid (8, 32, 16) = 4096 blocks (512 rows x 128-col slice, 2KB tile).
// Cross-block per-row min via order-inverted-key atomicMax (identity 0).
// Group ticket -> group max -> per-batch atomicMax -> global ticket ->
// final sum. All global state reset each call (graph-replay invariant).
// ---------------------------------------------------------------------------

#define NPOINT 4096
#define T      128                 // threads per block
#define RN     4                   // rows per thread
#define BN     (T * RN)            // 512 rows per block
#define ROWB   (NPOINT / BN)       // 8 row-blocks
#define CS     32                  // column splits
#define CPB    (NPOINT / CS)       // 128 cols per block
#define TM     CPB                 // tile = whole slice (2KB)
#define NGRP   16                  // B*2 (b,dir) groups
#define GBLK   (ROWB * CS)         // blocks per group = 256

#define FMA2(d, a, b, c) \
    asm("fma.rn.f32x2 %0, %1, %2, %3;" : "=l"(d) : "l"(a), "l"(b), "l"(c))
#define PACK2(o, x) \
    asm("mov.b64 %0, {%1, %1};" : "=l"(o) : "f"(x))
#define UNPACK2(lo, hi, v) \
    asm("mov.b64 {%0, %1}, %2;" : "=f"(lo), "=f"(hi) : "l"(v))

// Monotone map: smaller float <=> LARGER unsigned key (row min == atomicMax).
// Every real float maps to key > 0, so 0 is the identity/reset state.
__device__ __forceinline__ unsigned map_min(float f) {
    unsigned u = __float_as_uint(f);
    return ((int)u < 0) ? u : (~u & 0x7FFFFFFFu);
}
__device__ __forceinline__ float unmap_min(unsigned s) {
    return ((int)s < 0) ? __uint_as_float(s)
                        : __uint_as_float(~s & 0x7FFFFFFFu);
}

__device__ unsigned g_cmb[NGRP][NPOINT];  // combined row-min keys (reset 0)
__device__ int      g_grp[NGRP];          // per-group tickets (reset 0)
__device__ float    g_bmax[16];           // per-batch max >= 0 (reset 0)
__device__ int      g_done;               // finalizer ticket (reset 0)

__global__ void __launch_bounds__(T, 10)
hd_main(const float* __restrict__ p1, const float* __restrict__ p2,
        float* __restrict__ out, int nb) {
    const int tid = threadIdx.x;
    const int z   = blockIdx.z;          // b*2 + dir
    const int b   = z >> 1;
    const int dir = z & 1;

    const float* rows = (dir == 0 ? p1 : p2) + (size_t)b * NPOINT * 3;
    const float* cols = (dir == 0 ? p2 : p1) + (size_t)b * NPOINT * 3;

    // Per-thread row points, coords broadcast-packed for f32x2.
    // (x^2 recomputed from these in the epilogue - not live in the loop.)
    unsigned long long px0[RN], px1[RN], px2[RN];
    float rmE[RN], rmO[RN];

#pragma unroll
    for (int r = 0; r < RN; r++) {
        const int n = blockIdx.x * BN + r * T + tid;
        const float* pr = rows + (size_t)n * 3;
        PACK2(px0[r], pr[0]);
        PACK2(px1[r], pr[1]);
        PACK2(px2[r], pr[2]);
        rmE[r] = 3.4e38f;
        rmO[r] = 3.4e38f;
    }

    // Shared tile: col pair j -> entry 2j   = {-2y0[e],-2y0[o],-2y1[e],-2y1[o]}
    //                            entry 2j+1 = {-2y2[e],-2y2[o],  y2[e],  y2[o]}
    __shared__ ulonglong2 sAB[TM];
    __shared__ unsigned   sred[T / 32];

    {
        const int idx = tid;             // TM == T: one point per thread
        const float* pc = cols + (size_t)(blockIdx.y * CPB + idx) * 3;
        const float y0 = pc[0], y1 = pc[1], y2 = pc[2];
        const float ysq = y0 * y0 + y1 * y1 + y2 * y2;
        const int j = idx >> 1, l = idx & 1;
        float* A  = reinterpret_cast<float*>(&sAB[2 * j]);
        float* Bv = reinterpret_cast<float*>(&sAB[2 * j + 1]);
        A[l]      = -2.0f * y0;
        A[2 + l]  = -2.0f * y1;
        Bv[l]     = -2.0f * y2;
        Bv[2 + l] = ysq;
    }
    __syncthreads();

    const ulonglong2* sp = sAB;
#pragma unroll 8
    for (int j = 0; j < TM / 2; j++, sp += 2) {
        const ulonglong2 va = sp[0];
        const ulonglong2 vb = sp[1];
#pragma unroll
        for (int r = 0; r < RN; r++) {
            unsigned long long t0r, t1r, acc;
            FMA2(t0r, px2[r], vb.x, vb.y);   // -2*x2*y2 + y^2
            FMA2(t1r, px1[r], va.y, t0r);    // + -2*x1*y1
            FMA2(acc, px0[r], va.x, t1r);    // + -2*x0*y0
            float lo, hi;
            UNPACK2(lo, hi, acc);
            rmE[r] = fminf(rmE[r], lo);
            rmO[r] = fminf(rmO[r], hi);
        }
    }

    // Combine this slice's row mins into the global per-row key array.
#pragma unroll
    for (int r = 0; r < RN; r++) {
        const int n = blockIdx.x * BN + r * T + tid;
        float a0, a1, a2, dummy;
        UNPACK2(a0, dummy, px0[r]);
        UNPACK2(a1, dummy, px1[r]);
        UNPACK2(a2, dummy, px2[r]);
        const float xsq = a0 * a0 + a1 * a1 + a2 * a2;
        const float d = xsq + fminf(rmE[r], rmO[r]);
        atomicMax(&g_cmb[z][n], map_min(d));
    }
    __threadfence();
    __syncthreads();

    // Group ticket: last of the GBLK blocks in this (b,dir) finalizes.
    __shared__ int s_last;
    if (tid == 0)
        s_last = (atomicAdd(&g_grp[z], 1) == GBLK - 1);
    __syncthreads();
    if (!s_last) return;
    __threadfence();

    // Group finalize: max over rows of row-min == unmap(min over keys).
    unsigned kmin = 0xFFFFFFFFu;
    for (int i = tid; i < NPOINT; i += T) {
        kmin = min(kmin, g_cmb[z][i]);
        g_cmb[z][i] = 0u;                       // reset for next replay
    }
#pragma unroll
    for (int off = 16; off > 0; off >>= 1)
        kmin = min(kmin, __shfl_xor_sync(0xffffffffu, kmin, off));
    if ((tid & 31) == 0) sred[tid >> 5] = kmin;
    __syncthreads();

    if (tid == 0) {
        unsigned km = sred[0];
#pragma unroll
        for (int w = 1; w < T / 32; w++) km = min(km, sred[w]);
        float m = fmaxf(unmap_min(km), 0.0f);   // true max > 0
        atomicMax(reinterpret_cast<int*>(&g_bmax[b]), __float_as_int(m));
        g_grp[z] = 0;                           // reset group ticket
        __threadfence();
        if (atomicAdd(&g_done, 1) == NGRP - 1) {
            __threadfence();
            float s = 0.0f;
            for (int i = 0; i < nb; i++) {
                s += g_bmax[i];
                g_bmax[i] = 0.0f;               // reset
            }
            out[0] = s;
            __threadfence();
            atomicExch(&g_done, 0);             // reset
        }
    }
}

extern "C" void kernel_launch(void* const* d_in, const int* in_sizes, int n_in,
                              void* d_out, int out_size) {
    const float* p1 = (const float*)d_in[0];
    const float* p2 = (const float*)d_in[1];
    float* out = (float*)d_out;

    const int B = in_sizes[0] / (NPOINT * 3);
    dim3 grid(ROWB, CS, B * 2);
    hd_main<<<grid, T>>>(p1, p2, out, B);
}

// round 17
// speedup vs baseline: 1.0949x; 1.0427x over previous
#include <cuda_runtime.h>
#include <cstdint>

// ---------------------------------------------------------------------------
// HausdorffLoss: B=8, N=M=4096, 3-D points. Single fused dense kernel.
// d[b,n,m] = x2[n] + y2[m] - 2*dot(x_n, y_m)
// out = sum_b max( max_n min_m d, max_m min_n d )
//
// Round-17: RN=8 to amortize LDS + loop overhead (2.69 instr/dist vs 3.0).
// IPC measured occupancy-invariant (40-67%), so fewer instructions -> less
// time. __launch_bounds__(128,6) -> 84-reg budget (need ~80, no spills);
// xsq recomputed in the epilogue from packed px regs. grid (4,32,16)=2048
// fine-grained blocks (1024 rows x 128-col slice, 2KB tile).
// Cross-block per-row min via order-inverted-key atomicMax (identity 0).
// Group ticket -> group max -> per-batch atomicMax -> global ticket ->
// final sum. All global state reset each call (graph-replay invariant).
// ---------------------------------------------------------------------------

#define NPOINT 4096
#define T      128                 // threads per block
#define RN     8                   // rows per thread
#define BN     (T * RN)            // 1024 rows per block
#define ROWB   (NPOINT / BN)       // 4 row-blocks
#define CS     32                  // column splits
#define CPB    (NPOINT / CS)       // 128 cols per block
#define TM     CPB                 // tile = whole slice (2KB)
#define NGRP   16                  // B*2 (b,dir) groups
#define GBLK   (ROWB * CS)         // blocks per group = 128

#define FMA2(d, a, b, c) \
    asm("fma.rn.f32x2 %0, %1, %2, %3;" : "=l"(d) : "l"(a), "l"(b), "l"(c))
#define PACK2(o, x) \
    asm("mov.b64 %0, {%1, %1};" : "=l"(o) : "f"(x))
#define UNPACK2(lo, hi, v) \
    asm("mov.b64 {%0, %1}, %2;" : "=f"(lo), "=f"(hi) : "l"(v))

// Monotone map: smaller float <=> LARGER unsigned key (row min == atomicMax).
// Every real float maps to key > 0, so 0 is the identity/reset state.
__device__ __forceinline__ unsigned map_min(float f) {
    unsigned u = __float_as_uint(f);
    return ((int)u < 0) ? u : (~u & 0x7FFFFFFFu);
}
__device__ __forceinline__ float unmap_min(unsigned s) {
    return ((int)s < 0) ? __uint_as_float(s)
                        : __uint_as_float(~s & 0x7FFFFFFFu);
}

__device__ unsigned g_cmb[NGRP][NPOINT];  // combined row-min keys (reset 0)
__device__ int      g_grp[NGRP];          // per-group tickets (reset 0)
__device__ float    g_bmax[16];           // per-batch max >= 0 (reset 0)
__device__ int      g_done;               // finalizer ticket (reset 0)

__global__ void __launch_bounds__(T, 6)
hd_main(const float* __restrict__ p1, const float* __restrict__ p2,
        float* __restrict__ out, int nb) {
    const int tid = threadIdx.x;
    const int z   = blockIdx.z;          // b*2 + dir
    const int b   = z >> 1;
    const int dir = z & 1;

    const float* rows = (dir == 0 ? p1 : p2) + (size_t)b * NPOINT * 3;
    const float* cols = (dir == 0 ? p2 : p1) + (size_t)b * NPOINT * 3;

    // Per-thread row points, coords broadcast-packed for f32x2.
    // (x^2 recomputed from these in the epilogue - not live in the loop.)
    unsigned long long px0[RN], px1[RN], px2[RN];
    float rmE[RN], rmO[RN];

#pragma unroll
    for (int r = 0; r < RN; r++) {
        const int n = blockIdx.x * BN + r * T + tid;
        const float* pr = rows + (size_t)n * 3;
        PACK2(px0[r], pr[0]);
        PACK2(px1[r], pr[1]);
        PACK2(px2[r], pr[2]);
        rmE[r] = 3.4e38f;
        rmO[r] = 3.4e38f;
    }

    // Shared tile: col pair j -> entry 2j   = {-2y0[e],-2y0[o],-2y1[e],-2y1[o]}
    //                            entry 2j+1 = {-2y2[e],-2y2[o],  y2[e],  y2[o]}
    __shared__ ulonglong2 sAB[TM];
    __shared__ unsigned   sred[T / 32];

    {
        const int idx = tid;             // TM == T: one point per thread
        const float* pc = cols + (size_t)(blockIdx.y * CPB + idx) * 3;
        const float y0 = pc[0], y1 = pc[1], y2 = pc[2];
        const float ysq = y0 * y0 + y1 * y1 + y2 * y2;
        const int j = idx >> 1, l = idx & 1;
        float* A  = reinterpret_cast<float*>(&sAB[2 * j]);
        float* Bv = reinterpret_cast<float*>(&sAB[2 * j + 1]);
        A[l]      = -2.0f * y0;
        A[2 + l]  = -2.0f * y1;
        Bv[l]     = -2.0f * y2;
        Bv[2 + l] = ysq;
    }
    __syncthreads();

    const ulonglong2* sp = sAB;
#pragma unroll 4
    for (int j = 0; j < TM / 2; j++, sp += 2) {
        const ulonglong2 va = sp[0];
        const ulonglong2 vb = sp[1];
#pragma unroll
        for (int r = 0; r < RN; r++) {
            unsigned long long t0r, t1r, acc;
            FMA2(t0r, px2[r], vb.x, vb.y);   // -2*x2*y2 + y^2
            FMA2(t1r, px1[r], va.y, t0r);    // + -2*x1*y1
            FMA2(acc, px0[r], va.x, t1r);    // + -2*x0*y0
            float lo, hi;
            UNPACK2(lo, hi, acc);
            rmE[r] = fminf(rmE[r], lo);
            rmO[r] = fminf(rmO[r], hi);
        }
    }

    // Combine this slice's row mins into the global per-row key array.
#pragma unroll
    for (int r = 0; r < RN; r++) {
        const int n = blockIdx.x * BN + r * T + tid;
        float a0, a1, a2, dummy;
        UNPACK2(a0, dummy, px0[r]);
        UNPACK2(a1, dummy, px1[r]);
        UNPACK2(a2, dummy, px2[r]);
        const float xsq = a0 * a0 + a1 * a1 + a2 * a2;
        const float d = xsq + fminf(rmE[r], rmO[r]);
        atomicMax(&g_cmb[z][n], map_min(d));
    }
    __threadfence();
    __syncthreads();

    // Group ticket: last of the GBLK blocks in this (b,dir) finalizes.
    __shared__ int s_last;
    if (tid == 0)
        s_last = (atomicAdd(&g_grp[z], 1) == GBLK - 1);
    __syncthreads();
    if (!s_last) return;
    __threadfence();

    // Group finalize: max over rows of row-min == unmap(min over keys).
    unsigned kmin = 0xFFFFFFFFu;
    for (int i = tid; i < NPOINT; i += T) {
        kmin = min(kmin, g_cmb[z][i]);
        g_cmb[z][i] = 0u;                       // reset for next replay
    }
#pragma unroll
    for (int off = 16; off > 0; off >>= 1)
        kmin = min(kmin, __shfl_xor_sync(0xffffffffu, kmin, off));
    if ((tid & 31) == 0) sred[tid >> 5] = kmin;
    __syncthreads();

    if (tid == 0) {
        unsigned km = sred[0];
#pragma unroll
        for (int w = 1; w < T / 32; w++) km = min(km, sred[w]);
        float m = fmaxf(unmap_min(km), 0.0f);   // true max > 0
        atomicMax(reinterpret_cast<int*>(&g_bmax[b]), __float_as_int(m));
        g_grp[z] = 0;                           // reset group ticket
        __threadfence();
        if (atomicAdd(&g_done, 1) == NGRP - 1) {
            __threadfence();
            float s = 0.0f;
            for (int i = 0; i < nb; i++) {
                s += g_bmax[i];
                g_bmax[i] = 0.0f;               // reset
            }
            out[0] = s;
            __threadfence();
            atomicExch(&g_done, 0);             // reset
        }
    }
}

extern "C" void kernel_launch(void* const* d_in, const int* in_sizes, int n_in,
                              void* d_out, int out_size) {
    const float* p1 = (const float*)d_in[0];
    const float* p2 = (const float*)d_in[1];
    float* out = (float*)d_out;

    const int B = in_sizes[0] / (NPOINT * 3);
    dim3 grid(ROWB, CS, B * 2);
    hd_main<<<grid, T>>>(p1, p2, out, B);
}